// round 1
// baseline (speedup 1.0000x reference)
#include <cuda_runtime.h>
#include <math.h>

// Problem constants
constexpr int HDIM = 768;
constexpr int SEQ  = 256;
constexpr int NB   = 16;   // B
constexpr int NK   = 32;   // 2B

// GEMM tiling
constexpr int BM = 64;     // rows (q tokens) per CTA
constexpr int KC = 16;     // K-chunk

// Scratch for normalized embeddings (static device allocation: allowed)
__device__ float g_qn[NB * SEQ * HDIM];
__device__ float g_kn[NK * SEQ * HDIM];

// ---------------------------------------------------------------------------
// Kernel 0: zero the output (harness poisons it to 0xAA)
// ---------------------------------------------------------------------------
__global__ void zero_out_kernel(float* __restrict__ out) {
    out[threadIdx.x] = 0.0f;
}

// ---------------------------------------------------------------------------
// Kernel 1: L2-normalize each token (one 256-thread block per token)
// tokens 0..NB*SEQ-1 -> q, rest -> k
// ---------------------------------------------------------------------------
__global__ void normalize_kernel(const float* __restrict__ q,
                                 const float* __restrict__ k) {
    int tok = blockIdx.x;
    const float* src;
    float* dst;
    if (tok < NB * SEQ) {
        src = q + (size_t)tok * HDIM;
        dst = g_qn + (size_t)tok * HDIM;
    } else {
        int t2 = tok - NB * SEQ;
        src = k + (size_t)t2 * HDIM;
        dst = g_kn + (size_t)t2 * HDIM;
    }
    int tid = threadIdx.x;  // 256 threads, 3 elems each
    float v0 = src[tid];
    float v1 = src[tid + 256];
    float v2 = src[tid + 512];
    float ss = v0 * v0 + v1 * v1 + v2 * v2;
#pragma unroll
    for (int o = 16; o; o >>= 1) ss += __shfl_xor_sync(0xffffffffu, ss, o);
    __shared__ float red[8];
    if ((tid & 31) == 0) red[tid >> 5] = ss;
    __syncthreads();
    __shared__ float total;
    if (tid < 8) {
        float s = red[tid];
#pragma unroll
        for (int o = 4; o; o >>= 1) s += __shfl_xor_sync(0xffu, s, o);
        if (tid == 0) total = s;
    }
    __syncthreads();
    float inv = 1.0f / fmaxf(sqrtf(total), 1e-12f);
    dst[tid]       = v0 * inv;
    dst[tid + 256] = v1 * inv;
    dst[tid + 512] = v2 * inv;
}

// ---------------------------------------------------------------------------
// Kernel 2: fused per-pair GEMM + distance-weighted masked softmax + SUM(p*C)
//
// Grid: (4 m-blocks, NK, NB). Block: 256 threads = 8 warps.
// Warp w owns rows [8w, 8w+8) of the 64-row tile; lane owns cols lane+32*j.
// C never leaves registers: softmax over t and sum_t p*C done with shuffles.
// ---------------------------------------------------------------------------
__global__ __launch_bounds__(256, 2)
void li_pair_kernel(const float* __restrict__ plsc,
                    const float* __restrict__ paraw,
                    const int*   __restrict__ qmask,
                    const int*   __restrict__ kmask,
                    float*       __restrict__ out) {
    const int mb = blockIdx.x;   // 0..3
    const int jb = blockIdx.y;   // 0..NK-1
    const int ib = blockIdx.z;   // 0..NB-1
    const int tid  = threadIdx.x;
    const int lane = tid & 31;
    const int wid  = tid >> 5;

    __shared__ float As[2][BM][KC];        // [buf][row][k]  (row-major: f4 stores OK)
    __shared__ float Bs[2][KC][SEQ + 1];   // [buf][k][t]    (+1 pad: conflict-free)
    __shared__ float wtab[SEQ];
    __shared__ float warpsum[8];

    const float scale = expf(plsc[0]);
    const float ar    = paraw[0];
    const float alpha = ar >= 0.0f ? ar : 0.01f * ar;  // leaky_relu
    if (tid < SEQ) wtab[tid] = __expf(-alpha * (float)tid);

    const float* Ag = g_qn + (size_t)(ib * SEQ + mb * BM) * HDIM;
    const float* Bg = g_kn + (size_t)(jb * SEQ) * HDIM;

    const int arow = tid >> 2;          // 0..63
    const int akq  = (tid & 3) << 2;    // 0,4,8,12

    float acc[8][8];
#pragma unroll
    for (int r = 0; r < 8; r++)
#pragma unroll
        for (int j = 0; j < 8; j++) acc[r][j] = 0.0f;

    // ---- preload tile 0 into buffer 0 ----
    {
        float4 a = *(const float4*)(Ag + (size_t)arow * HDIM + akq);
        *(float4*)&As[0][arow][akq] = a;
#pragma unroll
        for (int c = 0; c < 4; c++) {
            int idx = tid + 256 * c;
            int t = idx >> 2, kq = (idx & 3) << 2;
            float4 b = *(const float4*)(Bg + (size_t)t * HDIM + kq);
            Bs[0][kq + 0][t] = b.x;
            Bs[0][kq + 1][t] = b.y;
            Bs[0][kq + 2][t] = b.z;
            Bs[0][kq + 3][t] = b.w;
        }
    }
    __syncthreads();

    // ---- main K loop, double-buffered ----
    const int NIT = HDIM / KC;  // 48
    for (int it = 0; it < NIT; ++it) {
        const int cur = it & 1;
        float4 pa;
        float4 pb[4];
        const bool more = (it + 1 < NIT);
        if (more) {
            const int k0 = (it + 1) * KC;
            pa = *(const float4*)(Ag + (size_t)arow * HDIM + k0 + akq);
#pragma unroll
            for (int c = 0; c < 4; c++) {
                int idx = tid + 256 * c;
                int t = idx >> 2, kq = (idx & 3) << 2;
                pb[c] = *(const float4*)(Bg + (size_t)t * HDIM + k0 + kq);
            }
        }
#pragma unroll
        for (int k = 0; k < KC; k++) {
            float a[8], b[8];
#pragma unroll
            for (int r = 0; r < 8; r++) a[r] = As[cur][wid * 8 + r][k];
#pragma unroll
            for (int j = 0; j < 8; j++) b[j] = Bs[cur][k][lane + 32 * j];
#pragma unroll
            for (int r = 0; r < 8; r++)
#pragma unroll
                for (int j = 0; j < 8; j++)
                    acc[r][j] = fmaf(a[r], b[j], acc[r][j]);
        }
        if (more) {
            const int nxt = cur ^ 1;
            *(float4*)&As[nxt][arow][akq] = pa;
#pragma unroll
            for (int c = 0; c < 4; c++) {
                int idx = tid + 256 * c;
                int t = idx >> 2, kq = (idx & 3) << 2;
                Bs[nxt][kq + 0][t] = pb[c].x;
                Bs[nxt][kq + 1][t] = pb[c].y;
                Bs[nxt][kq + 2][t] = pb[c].z;
                Bs[nxt][kq + 3][t] = pb[c].w;
            }
        }
        __syncthreads();
    }

    // ---- fused epilogue: masked dist-weighted softmax over t, then sum p*C ----
    const int* qm = qmask + ib * SEQ;
    const int* km = kmask + jb * SEQ;
    int kmv[8];
#pragma unroll
    for (int j = 0; j < 8; j++) kmv[j] = km[lane + 32 * j];

    float total = 0.0f;
#pragma unroll
    for (int r = 0; r < 8; r++) {
        const int s = mb * BM + wid * 8 + r;   // uniform across warp
        if (qm[s] == 0) continue;              // per_tok * q_mask
        float lg[8];
        float m = -INFINITY;
#pragma unroll
        for (int j = 0; j < 8; j++) {
            int t = lane + 32 * j;
            int d = s - t; d = d < 0 ? -d : d;
            float l = kmv[j] ? scale * acc[r][j] * wtab[d] : -INFINITY;
            lg[j] = l;
            m = fmaxf(m, l);
        }
#pragma unroll
        for (int o = 16; o; o >>= 1)
            m = fmaxf(m, __shfl_xor_sync(0xffffffffu, m, o));
        if (m == -INFINITY) continue;          // fully-masked row -> 0
        float den = 0.0f, num = 0.0f;
#pragma unroll
        for (int j = 0; j < 8; j++) {
            float e = kmv[j] ? __expf(lg[j] - m) : 0.0f;
            den += e;
            num += e * acc[r][j];
        }
#pragma unroll
        for (int o = 16; o; o >>= 1) {
            den += __shfl_xor_sync(0xffffffffu, den, o);
            num += __shfl_xor_sync(0xffffffffu, num, o);
        }
        total += num / den;
    }

    if (lane == 0) warpsum[wid] = total;
    __syncthreads();
    if (tid == 0) {
        float sum = 0.0f;
#pragma unroll
        for (int w = 0; w < 8; w++) sum += warpsum[w];
        atomicAdd(&out[ib * NK + jb], sum);
    }
}

// ---------------------------------------------------------------------------
// Launch
// ---------------------------------------------------------------------------
extern "C" void kernel_launch(void* const* d_in, const int* in_sizes, int n_in,
                              void* d_out, int out_size) {
    const float* q    = (const float*)d_in[0];  // [16,256,768] f32
    const float* k    = (const float*)d_in[1];  // [32,256,768] f32
    const float* lsc  = (const float*)d_in[2];  // scalar
    const float* araw = (const float*)d_in[3];  // scalar
    const int*   qm   = (const int*)d_in[4];    // [16,256] i32
    const int*   km   = (const int*)d_in[5];    // [32,256] i32
    float* out = (float*)d_out;                 // [16,32] f32

    zero_out_kernel<<<1, NB * NK>>>(out);
    normalize_kernel<<<NB * SEQ + NK * SEQ, 256>>>(q, k);
    dim3 grid(SEQ / BM, NK, NB);   // (4, 32, 16) = 2048 CTAs
    li_pair_kernel<<<grid, 256>>>(lsc, araw, qm, km, out);
}

// round 2
// speedup vs baseline: 1.0001x; 1.0001x over previous
#include <cuda_runtime.h>
#include <math.h>

// Problem constants
constexpr int HDIM = 768;
constexpr int SEQ  = 256;
constexpr int NB   = 16;   // B
constexpr int NK   = 32;   // 2B

// GEMM tiling
constexpr int BM = 64;     // rows (q tokens) per CTA
constexpr int KC = 16;     // K-chunk

// Scratch for normalized embeddings (static device allocation: allowed)
__device__ float g_qn[NB * SEQ * HDIM];
__device__ float g_kn[NK * SEQ * HDIM];

// ---------------------------------------------------------------------------
// Kernel 0: zero the output (harness poisons it to 0xAA)
// ---------------------------------------------------------------------------
__global__ void zero_out_kernel(float* __restrict__ out) {
    out[threadIdx.x] = 0.0f;
}

// ---------------------------------------------------------------------------
// Kernel 1: L2-normalize each token (one 256-thread block per token)
// tokens 0..NB*SEQ-1 -> q, rest -> k
// ---------------------------------------------------------------------------
__global__ void normalize_kernel(const float* __restrict__ q,
                                 const float* __restrict__ k) {
    int tok = blockIdx.x;
    const float* src;
    float* dst;
    if (tok < NB * SEQ) {
        src = q + (size_t)tok * HDIM;
        dst = g_qn + (size_t)tok * HDIM;
    } else {
        int t2 = tok - NB * SEQ;
        src = k + (size_t)t2 * HDIM;
        dst = g_kn + (size_t)t2 * HDIM;
    }
    int tid = threadIdx.x;  // 256 threads, 3 elems each
    float v0 = src[tid];
    float v1 = src[tid + 256];
    float v2 = src[tid + 512];
    float ss = v0 * v0 + v1 * v1 + v2 * v2;
#pragma unroll
    for (int o = 16; o; o >>= 1) ss += __shfl_xor_sync(0xffffffffu, ss, o);
    __shared__ float red[8];
    if ((tid & 31) == 0) red[tid >> 5] = ss;
    __syncthreads();
    __shared__ float total;
    if (tid < 8) {
        float s = red[tid];
#pragma unroll
        for (int o = 4; o; o >>= 1) s += __shfl_xor_sync(0xffu, s, o);
        if (tid == 0) total = s;
    }
    __syncthreads();
    float inv = 1.0f / fmaxf(sqrtf(total), 1e-12f);
    dst[tid]       = v0 * inv;
    dst[tid + 256] = v1 * inv;
    dst[tid + 512] = v2 * inv;
}

// ---------------------------------------------------------------------------
// Kernel 2: fused per-pair GEMM + distance-weighted masked softmax + SUM(p*C)
//
// Grid: (4 m-blocks, NK, NB). Block: 256 threads = 8 warps.
// Warp w owns rows [8w, 8w+8) of the 64-row tile; lane owns cols lane+32*j.
// C never leaves registers: softmax over t and sum_t p*C done with shuffles.
// ---------------------------------------------------------------------------
__global__ __launch_bounds__(256, 2)
void li_pair_kernel(const float* __restrict__ plsc,
                    const float* __restrict__ paraw,
                    const int*   __restrict__ qmask,
                    const int*   __restrict__ kmask,
                    float*       __restrict__ out) {
    const int mb = blockIdx.x;   // 0..3
    const int jb = blockIdx.y;   // 0..NK-1
    const int ib = blockIdx.z;   // 0..NB-1
    const int tid  = threadIdx.x;
    const int lane = tid & 31;
    const int wid  = tid >> 5;

    __shared__ float As[2][BM][KC];        // [buf][row][k]  (row-major: f4 stores OK)
    __shared__ float Bs[2][KC][SEQ + 1];   // [buf][k][t]    (+1 pad: conflict-free)
    __shared__ float wtab[SEQ];
    __shared__ float warpsum[8];

    const float scale = expf(plsc[0]);
    const float ar    = paraw[0];
    const float alpha = ar >= 0.0f ? ar : 0.01f * ar;  // leaky_relu
    if (tid < SEQ) wtab[tid] = __expf(-alpha * (float)tid);

    const float* Ag = g_qn + (size_t)(ib * SEQ + mb * BM) * HDIM;
    const float* Bg = g_kn + (size_t)(jb * SEQ) * HDIM;

    const int arow = tid >> 2;          // 0..63
    const int akq  = (tid & 3) << 2;    // 0,4,8,12

    float acc[8][8];
#pragma unroll
    for (int r = 0; r < 8; r++)
#pragma unroll
        for (int j = 0; j < 8; j++) acc[r][j] = 0.0f;

    // ---- preload tile 0 into buffer 0 ----
    {
        float4 a = *(const float4*)(Ag + (size_t)arow * HDIM + akq);
        *(float4*)&As[0][arow][akq] = a;
#pragma unroll
        for (int c = 0; c < 4; c++) {
            int idx = tid + 256 * c;
            int t = idx >> 2, kq = (idx & 3) << 2;
            float4 b = *(const float4*)(Bg + (size_t)t * HDIM + kq);
            Bs[0][kq + 0][t] = b.x;
            Bs[0][kq + 1][t] = b.y;
            Bs[0][kq + 2][t] = b.z;
            Bs[0][kq + 3][t] = b.w;
        }
    }
    __syncthreads();

    // ---- main K loop, double-buffered ----
    const int NIT = HDIM / KC;  // 48
    for (int it = 0; it < NIT; ++it) {
        const int cur = it & 1;
        float4 pa;
        float4 pb[4];
        const bool more = (it + 1 < NIT);
        if (more) {
            const int k0 = (it + 1) * KC;
            pa = *(const float4*)(Ag + (size_t)arow * HDIM + k0 + akq);
#pragma unroll
            for (int c = 0; c < 4; c++) {
                int idx = tid + 256 * c;
                int t = idx >> 2, kq = (idx & 3) << 2;
                pb[c] = *(const float4*)(Bg + (size_t)t * HDIM + k0 + kq);
            }
        }
#pragma unroll
        for (int k = 0; k < KC; k++) {
            float a[8], b[8];
#pragma unroll
            for (int r = 0; r < 8; r++) a[r] = As[cur][wid * 8 + r][k];
#pragma unroll
            for (int j = 0; j < 8; j++) b[j] = Bs[cur][k][lane + 32 * j];
#pragma unroll
            for (int r = 0; r < 8; r++)
#pragma unroll
                for (int j = 0; j < 8; j++)
                    acc[r][j] = fmaf(a[r], b[j], acc[r][j]);
        }
        if (more) {
            const int nxt = cur ^ 1;
            *(float4*)&As[nxt][arow][akq] = pa;
#pragma unroll
            for (int c = 0; c < 4; c++) {
                int idx = tid + 256 * c;
                int t = idx >> 2, kq = (idx & 3) << 2;
                Bs[nxt][kq + 0][t] = pb[c].x;
                Bs[nxt][kq + 1][t] = pb[c].y;
                Bs[nxt][kq + 2][t] = pb[c].z;
                Bs[nxt][kq + 3][t] = pb[c].w;
            }
        }
        __syncthreads();
    }

    // ---- fused epilogue: masked dist-weighted softmax over t, then sum p*C ----
    const int* qm = qmask + ib * SEQ;
    const int* km = kmask + jb * SEQ;
    int kmv[8];
#pragma unroll
    for (int j = 0; j < 8; j++) kmv[j] = km[lane + 32 * j];

    float total = 0.0f;
#pragma unroll
    for (int r = 0; r < 8; r++) {
        const int s = mb * BM + wid * 8 + r;   // uniform across warp
        if (qm[s] == 0) continue;              // per_tok * q_mask
        float lg[8];
        float m = -INFINITY;
#pragma unroll
        for (int j = 0; j < 8; j++) {
            int t = lane + 32 * j;
            int d = s - t; d = d < 0 ? -d : d;
            float l = kmv[j] ? scale * acc[r][j] * wtab[d] : -INFINITY;
            lg[j] = l;
            m = fmaxf(m, l);
        }
#pragma unroll
        for (int o = 16; o; o >>= 1)
            m = fmaxf(m, __shfl_xor_sync(0xffffffffu, m, o));
        if (m == -INFINITY) continue;          // fully-masked row -> 0
        float den = 0.0f, num = 0.0f;
#pragma unroll
        for (int j = 0; j < 8; j++) {
            float e = kmv[j] ? __expf(lg[j] - m) : 0.0f;
            den += e;
            num += e * acc[r][j];
        }
#pragma unroll
        for (int o = 16; o; o >>= 1) {
            den += __shfl_xor_sync(0xffffffffu, den, o);
            num += __shfl_xor_sync(0xffffffffu, num, o);
        }
        total += num / den;
    }

    if (lane == 0) warpsum[wid] = total;
    __syncthreads();
    if (tid == 0) {
        float sum = 0.0f;
#pragma unroll
        for (int w = 0; w < 8; w++) sum += warpsum[w];
        atomicAdd(&out[ib * NK + jb], sum);
    }
}

// ---------------------------------------------------------------------------
// Launch
// ---------------------------------------------------------------------------
extern "C" void kernel_launch(void* const* d_in, const int* in_sizes, int n_in,
                              void* d_out, int out_size) {
    const float* q    = (const float*)d_in[0];  // [16,256,768] f32
    const float* k    = (const float*)d_in[1];  // [32,256,768] f32
    const float* lsc  = (const float*)d_in[2];  // scalar
    const float* araw = (const float*)d_in[3];  // scalar
    const int*   qm   = (const int*)d_in[4];    // [16,256] i32
    const int*   km   = (const int*)d_in[5];    // [32,256] i32
    float* out = (float*)d_out;                 // [16,32] f32

    zero_out_kernel<<<1, NB * NK>>>(out);
    normalize_kernel<<<NB * SEQ + NK * SEQ, 256>>>(q, k);
    dim3 grid(SEQ / BM, NK, NB);   // (4, 32, 16) = 2048 CTAs
    li_pair_kernel<<<grid, 256>>>(lsc, araw, qm, km, out);
}

// round 4
// speedup vs baseline: 1.5575x; 1.5574x over previous
#include <cuda_runtime.h>
#include <cuda_bf16.h>
#include <cstdint>
#include <math.h>

constexpr int HDIM = 768;
constexpr int SEQ  = 256;
constexpr int NB   = 16;
constexpr int NK   = 32;
constexpr int KC   = 64;           // K per chunk (64 bf16 = 128B rows)
constexpr int NCHUNK = HDIM / KC;  // 12
constexpr int BM   = 64;
constexpr int THREADS = 512;

// hi/lo bf16 split of normalized embeddings
__device__ __nv_bfloat16 g_qh[NB * SEQ * HDIM];
__device__ __nv_bfloat16 g_ql[NB * SEQ * HDIM];
__device__ __nv_bfloat16 g_kh[NK * SEQ * HDIM];
__device__ __nv_bfloat16 g_kl[NK * SEQ * HDIM];

// smem layout (bytes): buffers then aux
constexpr int ROWS_PER_BUF = 64 + 64 + 256 + 256;       // Ah Al Bh Bl
constexpr int BUFSZ   = ROWS_PER_BUF * 128;             // 81920
constexpr int OFF_AUX  = 2 * BUFSZ;                     // 163840
constexpr int OFF_WTAB = OFF_AUX;                       // 256 f32
constexpr int OFF_KMF  = OFF_AUX + 1024;                // 256 f32
constexpr int OFF_NUM  = OFF_AUX + 2048;                // 64*8 f32
constexpr int OFF_DEN  = OFF_AUX + 4096;                // 64*8 f32
constexpr int OFF_WSUM = OFF_AUX + 6144;                // 2 f32
constexpr int SMEM_TOTAL = OFF_AUX + 6208;

__device__ __forceinline__ uint32_t smem_u32(const void* p) {
    uint32_t a;
    asm("{ .reg .u64 t; cvta.to.shared.u64 t, %1; cvt.u32.u64 %0, t; }" : "=r"(a) : "l"(p));
    return a;
}
#define CP_ASYNC(dst, src) \
    asm volatile("cp.async.cg.shared.global [%0], [%1], 16;" :: "r"(dst), "l"(src) : "memory")
#define CP_COMMIT() asm volatile("cp.async.commit_group;" ::: "memory")
#define CP_WAIT1()  asm volatile("cp.async.wait_group 1;" ::: "memory")
#define CP_WAIT0()  asm volatile("cp.async.wait_group 0;" ::: "memory")

__device__ __forceinline__ void ldsm4(uint32_t* r, uint32_t addr) {
    asm volatile("ldmatrix.sync.aligned.m8n8.x4.shared.b16 {%0,%1,%2,%3}, [%4];"
                 : "=r"(r[0]), "=r"(r[1]), "=r"(r[2]), "=r"(r[3]) : "r"(addr));
}
__device__ __forceinline__ void mma16816(float* d, const uint32_t* a, uint32_t b0, uint32_t b1) {
    asm volatile("mma.sync.aligned.m16n8k16.row.col.f32.bf16.bf16.f32 "
                 "{%0,%1,%2,%3}, {%4,%5,%6,%7}, {%8,%9}, {%0,%1,%2,%3};"
                 : "+f"(d[0]), "+f"(d[1]), "+f"(d[2]), "+f"(d[3])
                 : "r"(a[0]), "r"(a[1]), "r"(a[2]), "r"(a[3]), "r"(b0), "r"(b1));
}

__global__ void zero_out_kernel(float* __restrict__ out) { out[threadIdx.x] = 0.0f; }

__global__ void normalize_kernel(const float* __restrict__ q, const float* __restrict__ k) {
    int tok = blockIdx.x;
    const float* src;
    __nv_bfloat16 *dh, *dl;
    if (tok < NB * SEQ) {
        src = q + (size_t)tok * HDIM;
        dh = g_qh + (size_t)tok * HDIM; dl = g_ql + (size_t)tok * HDIM;
    } else {
        int t2 = tok - NB * SEQ;
        src = k + (size_t)t2 * HDIM;
        dh = g_kh + (size_t)t2 * HDIM; dl = g_kl + (size_t)t2 * HDIM;
    }
    int tid = threadIdx.x;
    float v[3];
    float ss = 0.0f;
#pragma unroll
    for (int e = 0; e < 3; e++) { v[e] = src[tid + 256 * e]; ss += v[e] * v[e]; }
#pragma unroll
    for (int o = 16; o; o >>= 1) ss += __shfl_xor_sync(0xffffffffu, ss, o);
    __shared__ float red[8];
    __shared__ float total;
    if ((tid & 31) == 0) red[tid >> 5] = ss;
    __syncthreads();
    if (tid < 8) {
        float s = red[tid];
#pragma unroll
        for (int o = 4; o; o >>= 1) s += __shfl_xor_sync(0xffu, s, o);
        if (tid == 0) total = s;
    }
    __syncthreads();
    float inv = 1.0f / fmaxf(sqrtf(total), 1e-12f);
#pragma unroll
    for (int e = 0; e < 3; e++) {
        int idx = tid + 256 * e;
        float x = v[e] * inv;
        __nv_bfloat16 h = __float2bfloat16(x);
        dh[idx] = h;
        dl[idx] = __float2bfloat16(x - __bfloat162float(h));
    }
}

__global__ __launch_bounds__(THREADS, 1)
void li_hmma(const float* __restrict__ plsc, const float* __restrict__ paraw,
             const int* __restrict__ qmask, const int* __restrict__ kmask,
             float* __restrict__ out) {
    extern __shared__ __align__(128) char smem[];
    const uint32_t sb = smem_u32(smem);
    const int tid = threadIdx.x, lane = tid & 31, wid = tid >> 5;
    const int mb = blockIdx.x, jb = blockIdx.y, ib = blockIdx.z;

    float* wt = (float*)(smem + OFF_WTAB);
    float* kf = (float*)(smem + OFF_KMF);
    float* nums = (float*)(smem + OFF_NUM);
    float* dens = (float*)(smem + OFF_DEN);
    float* wsum = (float*)(smem + OFF_WSUM);

    const float scale = __expf(plsc[0]);
    const float ar = paraw[0];
    const float alpha = ar >= 0.0f ? ar : 0.01f * ar;
    if (tid < SEQ) {
        wt[tid] = __expf(-alpha * (float)tid);
        kf[tid] = (float)kmask[jb * SEQ + tid];
    }

    // ---- loader setup: thread owns row u0 = tid (all), u1 = tid+512 (tid<128)
    const int aq = ib * SEQ + mb * BM;
    const int bk = jb * SEQ;
    auto row_ptr = [&](int u) -> const __nv_bfloat16* {
        if (u < 64)  return g_qh + (size_t)(aq + u) * HDIM;
        if (u < 128) return g_ql + (size_t)(aq + u - 64) * HDIM;
        if (u < 384) return g_kh + (size_t)(bk + u - 128) * HDIM;
        return g_kl + (size_t)(bk + u - 384) * HDIM;
    };
    const int u0 = tid;
    const int u1 = tid + 512;
    const __nv_bfloat16* p0 = row_ptr(u0);
    const __nv_bfloat16* p1 = (tid < 128) ? row_ptr(u1) : nullptr;
    const uint32_t sw0 = (uint32_t)(u0 & 7), sw1 = (uint32_t)(u1 & 7);

    auto issue = [&](int it, int b) {
        const uint32_t base = sb + (uint32_t)b * BUFSZ;
        const uint32_t d0 = base + (uint32_t)u0 * 128u;
        const __nv_bfloat16* s0 = p0 + it * KC;
#pragma unroll
        for (uint32_t f = 0; f < 8; f++)
            CP_ASYNC(d0 + ((f ^ sw0) << 4), (const char*)(s0 + f * 8));
        if (tid < 128) {
            const uint32_t d1 = base + (uint32_t)u1 * 128u;
            const __nv_bfloat16* s1 = p1 + it * KC;
#pragma unroll
            for (uint32_t f = 0; f < 8; f++)
                CP_ASYNC(d1 + ((f ^ sw1) << 4), (const char*)(s1 + f * 8));
        }
    };

    // ---- MMA state ----
    const int mw = wid >> 3, nw = wid & 7;        // 2 x 8 warp grid
    const int l15 = lane & 15, lhi = lane >> 4;
    float acc[2][4][4];
#pragma unroll
    for (int im = 0; im < 2; im++)
#pragma unroll
        for (int tl = 0; tl < 4; tl++)
#pragma unroll
            for (int c = 0; c < 4; c++) acc[im][tl][c] = 0.0f;

    auto compute = [&](int b) {
        const uint32_t base = sb + (uint32_t)b * BUFSZ;
        const uint32_t sAh = base, sAl = base + 64u * 128u;
        const uint32_t sBh = base + 128u * 128u, sBl = base + 384u * 128u;
#pragma unroll
        for (int ks = 0; ks < 4; ks++) {
            const uint32_t kc = (uint32_t)(2 * ks + lhi);
            uint32_t ah[2][4], al[2][4], bh[2][4], bl[2][4];
#pragma unroll
            for (int im = 0; im < 2; im++) {
                const uint32_t ro = (uint32_t)(mw * 32 + im * 16 + l15);
                const uint32_t off = ro * 128u + ((kc ^ (ro & 7u)) << 4);
                ldsm4(ah[im], sAh + off);
                ldsm4(al[im], sAl + off);
            }
#pragma unroll
            for (int in = 0; in < 2; in++) {
                const uint32_t ro = (uint32_t)(nw * 32 + in * 16 + l15);
                const uint32_t off = ro * 128u + ((kc ^ (ro & 7u)) << 4);
                ldsm4(bh[in], sBh + off);
                ldsm4(bl[in], sBl + off);
            }
#pragma unroll
            for (int im = 0; im < 2; im++)
#pragma unroll
                for (int tl = 0; tl < 4; tl++) {
                    const int in = tl >> 1, o = tl & 1;
                    const uint32_t h0 = bh[in][o], h1 = bh[in][o + 2];
                    const uint32_t l0 = bl[in][o], l1 = bl[in][o + 2];
                    mma16816(acc[im][tl], ah[im], h0, h1);
                    mma16816(acc[im][tl], al[im], h0, h1);
                    mma16816(acc[im][tl], ah[im], l0, l1);
                }
        }
    };

    // ---- pipeline ----
    issue(0, 0); CP_COMMIT();
    issue(1, 1); CP_COMMIT();
#pragma unroll 1
    for (int it = 0; it < NCHUNK; ++it) {
        if (it == NCHUNK - 1) CP_WAIT0(); else CP_WAIT1();
        __syncthreads();
        compute(it & 1);
        __syncthreads();
        if (it + 2 < NCHUNK) { issue(it + 2, it & 1); CP_COMMIT(); }
    }

    // ---- epilogue: softmax (no max-sub, |logit| <= scale ~ 14.3) + sum p*C ----
    float pn[4] = {0, 0, 0, 0}, pd[4] = {0, 0, 0, 0};
    const int colb = nw * 32 + 2 * (lane & 3);
    const int rowq = lane >> 2;
#pragma unroll
    for (int im = 0; im < 2; im++)
#pragma unroll
        for (int hi = 0; hi < 2; hi++) {
            const int r = mw * 32 + im * 16 + hi * 8 + rowq;
            const int s = mb * BM + r;
            const int slot = im * 2 + hi;
#pragma unroll
            for (int tl = 0; tl < 4; tl++)
#pragma unroll
                for (int e = 0; e < 2; e++) {
                    const float C = acc[im][tl][hi * 2 + e];
                    const int t = colb + tl * 8 + e;
                    int d = s - t; d = d < 0 ? -d : d;
                    const float ex = kf[t] * __expf(scale * wt[d] * C);
                    pd[slot] += ex;
                    pn[slot] += ex * C;
                }
        }
#pragma unroll
    for (int o = 1; o <= 2; o <<= 1)
#pragma unroll
        for (int k = 0; k < 4; k++) {
            pn[k] += __shfl_xor_sync(0xffffffffu, pn[k], o);
            pd[k] += __shfl_xor_sync(0xffffffffu, pd[k], o);
        }
    if ((lane & 3) == 0)
#pragma unroll
        for (int k = 0; k < 4; k++) {
            const int r = mw * 32 + (k >> 1) * 16 + (k & 1) * 8 + rowq;
            nums[r * 8 + nw] = pn[k];
            dens[r * 8 + nw] = pd[k];
        }
    __syncthreads();
    if (tid < 64) {
        float n = 0.0f, d = 0.0f;
#pragma unroll
        for (int w = 0; w < 8; w++) { n += nums[tid * 8 + w]; d += dens[tid * 8 + w]; }
        float pt = d > 0.0f ? n / d : 0.0f;
        pt *= (float)qmask[ib * SEQ + mb * BM + tid];
#pragma unroll
        for (int o = 16; o; o >>= 1) pt += __shfl_xor_sync(0xffffffffu, pt, o);
        if (lane == 0) wsum[tid >> 5] = pt;
    }
    __syncthreads();
    if (tid == 0) atomicAdd(&out[ib * NK + jb], wsum[0] + wsum[1]);
}

extern "C" void kernel_launch(void* const* d_in, const int* in_sizes, int n_in,
                              void* d_out, int out_size) {
    const float* q    = (const float*)d_in[0];
    const float* k    = (const float*)d_in[1];
    const float* lsc  = (const float*)d_in[2];
    const float* araw = (const float*)d_in[3];
    const int*   qm   = (const int*)d_in[4];
    const int*   km   = (const int*)d_in[5];
    float* out = (float*)d_out;

    cudaFuncSetAttribute(li_hmma, cudaFuncAttributeMaxDynamicSharedMemorySize, SMEM_TOTAL);
    zero_out_kernel<<<1, NB * NK>>>(out);
    normalize_kernel<<<NB * SEQ + NK * SEQ, 256>>>(q, k);
    li_hmma<<<dim3(SEQ / BM, NK, NB), THREADS, SMEM_TOTAL>>>(lsc, araw, qm, km, out);
}